// round 1
// baseline (speedup 1.0000x reference)
#include <cuda_runtime.h>
#include <cuda_bf16.h>
#include <cstdint>

#define B_SZ   16
#define NPTS   32768
#define DFEAT  256
#define EDIM   512
#define KSEL   512
#define HEADS  8
#define DH     64
#define TOUT   16

// ------------------------- scratch (device globals, no allocs) ----------------
__device__ int   g_idx[B_SZ * KSEL];
__device__ float g_x [B_SZ * KSEL * EDIM];   // 16 MB
__device__ float g_k [B_SZ * KSEL * EDIM];   // 16 MB
__device__ float g_v [B_SZ * KSEL * EDIM];   // 16 MB
__device__ float g_q [B_SZ * TOUT * EDIM];
__device__ float g_o [B_SZ * TOUT * EDIM];
__device__ float g_o2[B_SZ * TOUT * EDIM];
__device__ float g_y [B_SZ * TOUT * EDIM];
__device__ float g_z [B_SZ * TOUT * EDIM];

// ------------------------- top-k (exact, sorted like lax.top_k) ---------------
__device__ __forceinline__ unsigned int f2u(float f) {
    unsigned int u = __float_as_uint(f);
    return (u & 0x80000000u) ? ~u : (u | 0x80000000u);  // monotone: bigger float -> bigger uint
}

__global__ void topk_kernel(const float* __restrict__ scores, int* __restrict__ out_idx) {
    const int b = blockIdx.x;
    const float* s = scores + (size_t)b * NPTS;
    __shared__ unsigned int hist[256];
    __shared__ unsigned int sh_prefix;
    __shared__ int sh_k;
    __shared__ int n_gt, n_eq;
    __shared__ unsigned long long keys[KSEL];
    __shared__ unsigned int eqi[KSEL];
    const int tid = threadIdx.x;   // blockDim = 256

    if (tid == 0) { sh_prefix = 0u; sh_k = KSEL; }
    __syncthreads();

    // exact radix-select of the 512th-largest value, 8 bits/round
    for (int shift = 24; shift >= 0; shift -= 8) {
        hist[tid] = 0u;
        __syncthreads();
        unsigned int pref = sh_prefix;
        unsigned int mhi = (shift == 24) ? 0u : (0xFFFFFFFFu << (shift + 8));
        for (int i = tid; i < NPTS; i += 256) {
            unsigned int u = f2u(s[i]);
            if ((u & mhi) == pref) atomicAdd(&hist[(u >> shift) & 0xFFu], 1u);
        }
        __syncthreads();
        if (tid == 0) {
            int rem = sh_k;
            int byte = 255;
            for (; byte > 0; byte--) {
                int c = (int)hist[byte];
                if (rem <= c) break;
                rem -= c;
            }
            sh_k = rem;
            sh_prefix = pref | ((unsigned int)byte << shift);
        }
        __syncthreads();
    }
    const unsigned int uth = sh_prefix;

    if (tid == 0) { n_gt = 0; n_eq = 0; }
    __syncthreads();
    for (int i = tid; i < NPTS; i += 256) {
        unsigned int u = f2u(s[i]);
        if (u > uth) {
            int p = atomicAdd(&n_gt, 1);
            keys[p] = ((unsigned long long)u << 32) | (unsigned int)(~i);
        } else if (u == uth) {
            int p = atomicAdd(&n_eq, 1);
            if (p < KSEL) eqi[p] = (unsigned int)i;
        }
    }
    __syncthreads();
    const int cgt = n_gt;
    const int ceq = n_eq < KSEL ? n_eq : KSEL;
    for (int i = tid; i < KSEL; i += 256) if (i >= ceq) eqi[i] = 0xFFFFFFFFu;
    __syncthreads();
    // ascending bitonic sort of tie indices (take smallest indices first)
    for (int size = 2; size <= KSEL; size <<= 1)
        for (int stride = size >> 1; stride >= 1; stride >>= 1) {
            __syncthreads();
            int low = tid & (stride - 1);
            int i = ((tid - low) << 1) | low;
            int j = i | stride;
            unsigned int a = eqi[i], c = eqi[j];
            bool asc = ((i & size) == 0);
            if (asc ? (a > c) : (a < c)) { eqi[i] = c; eqi[j] = a; }
        }
    __syncthreads();
    const int need = KSEL - cgt;
    for (int t = tid; t < need; t += 256)
        keys[cgt + t] = ((unsigned long long)uth << 32) | (unsigned int)(~eqi[t]);
    __syncthreads();
    // descending bitonic sort of (value, ~idx) -> exactly lax.top_k order
    for (int size = 2; size <= KSEL; size <<= 1)
        for (int stride = size >> 1; stride >= 1; stride >>= 1) {
            __syncthreads();
            int low = tid & (stride - 1);
            int i = ((tid - low) << 1) | low;
            int j = i | stride;
            unsigned long long a = keys[i], c = keys[j];
            bool desc = ((i & size) == 0);
            if (desc ? (a < c) : (a > c)) { keys[i] = c; keys[j] = a; }
        }
    __syncthreads();
    for (int i = tid; i < KSEL; i += 256)
        out_idx[b * KSEL + i] = (int)(~(unsigned int)(keys[i] & 0xFFFFFFFFu));
}

// ------------------------- generic tiled SGEMM: C = A @ Bw^T + bias ----------
// MODE 0: A row r = A + r*Kd
// MODE 1: A row r = gsrc[b, gidx[r], :] with b = r>>9 (gather path, Kd = 256)
// MODE 2: A row r = A + ((r>>4)*KSEL + (r&15))*Kd   (first-16-rows-of-x path)
template<int MODE>
__global__ void __launch_bounds__(256)
sgemm_kernel(const float* __restrict__ A,
             const float* __restrict__ Bw,
             const float* __restrict__ bias,
             float* __restrict__ C,
             int M, int Nc, int Kd,
             const int* __restrict__ gidx,
             const float* __restrict__ gsrc)
{
    __shared__ float s_a[16][64];
    __shared__ float s_b[16][64];
    const int tid = threadIdx.x;
    const int tx = tid & 15, ty = tid >> 4;
    const int bm = blockIdx.x * 64, bn = blockIdx.y * 64;
    const int lm = tid & 63;
    const int lk = (tid >> 6) << 2;

    const float* arow;
    {
        int r = bm + lm;
        if (MODE == 0) {
            arow = A + (size_t)r * Kd;
        } else if (MODE == 1) {
            int bb = r >> 9;
            arow = gsrc + ((size_t)bb * NPTS + (size_t)gidx[r]) * DFEAT;
        } else {
            int bb = r >> 4, t = r & 15;
            arow = A + ((size_t)(bb * KSEL + t)) * Kd;
        }
    }
    const float* brow = Bw + (size_t)(bn + lm) * Kd;

    float acc[4][4] = {};
    for (int k0 = 0; k0 < Kd; k0 += 16) {
        float4 a4 = *(const float4*)(arow + k0 + lk);
        float4 b4 = *(const float4*)(brow + k0 + lk);
        __syncthreads();
        s_a[lk + 0][lm] = a4.x; s_a[lk + 1][lm] = a4.y;
        s_a[lk + 2][lm] = a4.z; s_a[lk + 3][lm] = a4.w;
        s_b[lk + 0][lm] = b4.x; s_b[lk + 1][lm] = b4.y;
        s_b[lk + 2][lm] = b4.z; s_b[lk + 3][lm] = b4.w;
        __syncthreads();
        #pragma unroll
        for (int kk = 0; kk < 16; kk++) {
            float4 av = *(const float4*)&s_a[kk][ty << 2];
            float4 bv = *(const float4*)&s_b[kk][tx << 2];
            float ar[4] = {av.x, av.y, av.z, av.w};
            float br[4] = {bv.x, bv.y, bv.z, bv.w};
            #pragma unroll
            for (int i = 0; i < 4; i++)
                #pragma unroll
                for (int j = 0; j < 4; j++)
                    acc[i][j] += ar[i] * br[j];
        }
    }
    #pragma unroll
    for (int i = 0; i < 4; i++) {
        int row = bm + (ty << 2) + i;
        #pragma unroll
        for (int j = 0; j < 4; j++) {
            int col = bn + (tx << 2) + j;
            C[(size_t)row * Nc + col] = acc[i][j] + bias[col];
        }
    }
}

// ------------------------- attention (16 queries x 512 keys per (b,h)) -------
#define ATTN_SMEM ((16*64 + 16*512 + 128*65) * 4)

__global__ void attn_kernel(const float* __restrict__ qb, const float* __restrict__ kb,
                            const float* __restrict__ vb, float* __restrict__ ob)
{
    extern __shared__ float sm[];
    float* s_q  = sm;                       // 16 x 64
    float* s_l  = sm + 16 * 64;             // 16 x 512 logits / probs
    float* s_kv = sm + 16 * 64 + 16 * 512;  // 128 x 65 (padded)
    const int b = blockIdx.x >> 3, h = blockIdx.x & 7;
    const int tid = threadIdx.x;            // 128 threads

    const float* qbase = qb + ((size_t)b * TOUT) * EDIM + h * DH;
    for (int i = tid; i < 16 * 64; i += 128) {
        int t = i >> 6, d = i & 63;
        s_q[i] = qbase[(size_t)t * EDIM + d];
    }
    const float scale = 0.125f;  // 1/sqrt(64)

    for (int c = 0; c < 4; c++) {
        const float* kbase = kb + ((size_t)(b * KSEL + c * 128)) * EDIM + h * DH;
        __syncthreads();
        for (int i = tid; i < 128 * 64; i += 128) {
            int j = i >> 6, d = i & 63;
            s_kv[j * 65 + d] = kbase[(size_t)j * EDIM + d];
        }
        __syncthreads();
        {   // thread tid handles key j = tid for all 16 queries
            int j = tid;
            float acc[16];
            #pragma unroll
            for (int t = 0; t < 16; t++) acc[t] = 0.f;
            for (int d = 0; d < 64; d++) {
                float kd = s_kv[j * 65 + d];
                #pragma unroll
                for (int t = 0; t < 16; t++) acc[t] += s_q[t * 64 + d] * kd;
            }
            #pragma unroll
            for (int t = 0; t < 16; t++) s_l[t * 512 + c * 128 + j] = acc[t] * scale;
        }
    }
    __syncthreads();

    // softmax: 8 lanes per row
    {
        int row = tid >> 3, l = tid & 7;
        float* lr = s_l + row * 512;
        float m = -1e30f;
        for (int j = l; j < 512; j += 8) m = fmaxf(m, lr[j]);
        for (int o = 4; o >= 1; o >>= 1) m = fmaxf(m, __shfl_xor_sync(0xffffffffu, m, o));
        float sum = 0.f;
        for (int j = l; j < 512; j += 8) { float e = expf(lr[j] - m); lr[j] = e; sum += e; }
        for (int o = 4; o >= 1; o >>= 1) sum += __shfl_xor_sync(0xffffffffu, sum, o);
        float inv = 1.f / sum;
        for (int j = l; j < 512; j += 8) lr[j] *= inv;
    }

    // o[t][d] = sum_j p[t][j] * v[j][d]
    {
        int d = tid & 63, tb = (tid >> 6) << 3;
        float acc[8];
        #pragma unroll
        for (int t = 0; t < 8; t++) acc[t] = 0.f;
        for (int c = 0; c < 4; c++) {
            const float* vbase = vb + ((size_t)(b * KSEL + c * 128)) * EDIM + h * DH;
            __syncthreads();
            for (int i = tid; i < 128 * 64; i += 128) {
                int j = i >> 6, dd = i & 63;
                s_kv[j * 65 + dd] = vbase[(size_t)j * EDIM + dd];
            }
            __syncthreads();
            for (int j = 0; j < 128; j++) {
                float vv = s_kv[j * 65 + d];
                #pragma unroll
                for (int t = 0; t < 8; t++) acc[t] += s_l[(tb + t) * 512 + c * 128 + j] * vv;
            }
        }
        float* obase = ob + ((size_t)b * TOUT) * EDIM + h * DH;
        #pragma unroll
        for (int t = 0; t < 8; t++) obase[(size_t)(tb + t) * EDIM + d] = acc[t];
    }
}

// ------------------------- residual + layernorm ------------------------------
__global__ void ln_kernel(const float* __restrict__ x, const float* __restrict__ o2,
                          const float* __restrict__ g, const float* __restrict__ be,
                          float* __restrict__ y)
{
    const int r = blockIdx.x;            // 0..255
    const int b = r >> 4, t = r & 15;
    const float* xr = x + ((size_t)(b * KSEL + t)) * EDIM;
    const float* orow = o2 + (size_t)r * EDIM;
    const int tid = threadIdx.x;         // 256
    float v0 = xr[tid] + orow[tid];
    float v1 = xr[tid + 256] + orow[tid + 256];
    float s = v0 + v1, sq = v0 * v0 + v1 * v1;
    for (int o = 16; o >= 1; o >>= 1) {
        s  += __shfl_xor_sync(0xffffffffu, s, o);
        sq += __shfl_xor_sync(0xffffffffu, sq, o);
    }
    __shared__ float ss[8], ssq[8];
    __shared__ float mu, rstd;
    int w = tid >> 5;
    if ((tid & 31) == 0) { ss[w] = s; ssq[w] = sq; }
    __syncthreads();
    if (tid == 0) {
        float S = 0.f, SQ = 0.f;
        for (int i = 0; i < 8; i++) { S += ss[i]; SQ += ssq[i]; }
        float m = S / 512.f;
        float var = SQ / 512.f - m * m;
        mu = m; rstd = rsqrtf(var + 1e-5f);
    }
    __syncthreads();
    y[(size_t)r * EDIM + tid]       = (v0 - mu) * rstd * g[tid]       + be[tid];
    y[(size_t)r * EDIM + tid + 256] = (v1 - mu) * rstd * g[tid + 256] + be[tid + 256];
}

// ------------------------- FFN residual + exact GELU -------------------------
__global__ void final_kernel(const float* __restrict__ y, const float* __restrict__ z,
                             float* __restrict__ out)
{
    int i = blockIdx.x * blockDim.x + threadIdx.x;  // 131072 total
    float zz = z[i];
    float ge = 0.5f * zz * (1.f + erff(zz * 0.70710678118654752f));
    out[i] = y[i] + ge;
}

// ------------------------- launcher ------------------------------------------
extern "C" void kernel_launch(void* const* d_in, const int* in_sizes, int n_in,
                              void* d_out, int out_size)
{
    const float* ppf = (const float*)d_in[0];
    const float* sc  = (const float*)d_in[1];
    const float* pw  = (const float*)d_in[2];
    const float* pb  = (const float*)d_in[3];
    const float* ipw = (const float*)d_in[4];
    const float* ipb = (const float*)d_in[5];
    const float* opw = (const float*)d_in[6];
    const float* opb = (const float*)d_in[7];
    const float* lng = (const float*)d_in[8];
    const float* lnb = (const float*)d_in[9];
    const float* fw  = (const float*)d_in[10];
    const float* fb  = (const float*)d_in[11];
    float* out = (float*)d_out;

    int* idx; float *x, *k, *v, *q, *o, *o2, *y, *z;
    cudaGetSymbolAddress((void**)&idx, g_idx);
    cudaGetSymbolAddress((void**)&x,  g_x);
    cudaGetSymbolAddress((void**)&k,  g_k);
    cudaGetSymbolAddress((void**)&v,  g_v);
    cudaGetSymbolAddress((void**)&q,  g_q);
    cudaGetSymbolAddress((void**)&o,  g_o);
    cudaGetSymbolAddress((void**)&o2, g_o2);
    cudaGetSymbolAddress((void**)&y,  g_y);
    cudaGetSymbolAddress((void**)&z,  g_z);

    // 1) exact sorted top-512 indices per batch
    topk_kernel<<<16, 256>>>(sc, idx);

    // 2) x = gather(feats) @ proj_w^T + proj_b      [8192, 512]
    sgemm_kernel<1><<<dim3(128, 8), 256>>>(nullptr, pw, pb, x, 8192, 512, 256, idx, ppf);

    // 3) k, v for all 512 tokens                    [8192, 512] each
    sgemm_kernel<0><<<dim3(128, 8), 256>>>(x, ipw + 512 * 512,  ipb + 512,  k, 8192, 512, 512, nullptr, nullptr);
    sgemm_kernel<0><<<dim3(128, 8), 256>>>(x, ipw + 1024 * 512, ipb + 1024, v, 8192, 512, 512, nullptr, nullptr);

    // 4) q only for the first 16 tokens per batch   [256, 512]
    sgemm_kernel<2><<<dim3(4, 8), 256>>>(x, ipw, ipb, q, 256, 512, 512, nullptr, nullptr);

    // 5) attention (16 queries x 512 keys) per (b, h)
    cudaFuncSetAttribute(attn_kernel, cudaFuncAttributeMaxDynamicSharedMemorySize, ATTN_SMEM);
    attn_kernel<<<128, 128, ATTN_SMEM>>>(q, k, v, o);

    // 6) out_proj on 256 rows
    sgemm_kernel<0><<<dim3(4, 8), 256>>>(o, opw, opb, o2, 256, 512, 512, nullptr, nullptr);

    // 7) residual + layernorm (256 rows)
    ln_kernel<<<256, 256>>>(x, o2, lng, lnb, y);

    // 8) FFN GEMM + 9) residual + exact GELU -> output [16,16,512]
    sgemm_kernel<0><<<dim3(4, 8), 256>>>(y, fw, fb, z, 256, 512, 512, nullptr, nullptr);
    final_kernel<<<512, 256>>>(y, z, out);
}

// round 3
// speedup vs baseline: 1.7324x; 1.7324x over previous
#include <cuda_runtime.h>
#include <cuda_bf16.h>
#include <cstdint>

#define B_SZ   16
#define NPTS   32768
#define DFEAT  256
#define EDIM   512
#define KSEL   512
#define HEADS  8
#define DH     64
#define TOUT   16

// ------------------------- scratch (device globals, no allocs) ----------------
__device__ int   g_idx[B_SZ * KSEL];
__device__ __nv_bfloat16 g_ahi[B_SZ * KSEL * DFEAT];
__device__ __nv_bfloat16 g_alo[B_SZ * KSEL * DFEAT];
__device__ __nv_bfloat16 g_wphi[EDIM * DFEAT];
__device__ __nv_bfloat16 g_wplo[EDIM * DFEAT];
__device__ __nv_bfloat16 g_wkhi[EDIM * EDIM];
__device__ __nv_bfloat16 g_wklo[EDIM * EDIM];
__device__ __nv_bfloat16 g_wvhi[EDIM * EDIM];
__device__ __nv_bfloat16 g_wvlo[EDIM * EDIM];
__device__ __nv_bfloat16 g_xhi[B_SZ * KSEL * EDIM];
__device__ __nv_bfloat16 g_xlo[B_SZ * KSEL * EDIM];
__device__ float g_k [B_SZ * KSEL * EDIM];   // 16 MB
__device__ float g_v [B_SZ * KSEL * EDIM];   // 16 MB
__device__ float g_xq[B_SZ * TOUT * EDIM];   // fp32 x, first 16 rows per batch
__device__ float g_q [B_SZ * TOUT * EDIM];
__device__ float g_o [B_SZ * TOUT * EDIM];
__device__ float g_o2[B_SZ * TOUT * EDIM];
__device__ float g_y [B_SZ * TOUT * EDIM];
__device__ float g_z [B_SZ * TOUT * EDIM];

// ------------------------- helpers -------------------------------------------
__device__ __forceinline__ uint32_t smem_u32(const void* p) {
    uint32_t a;
    asm("{ .reg .u64 t; cvta.to.shared.u64 t, %1; cvt.u32.u64 %0, t; }" : "=r"(a) : "l"(p));
    return a;
}
#define SWZ(off) ((off) ^ (((off) >> 3) & 0x70))

__device__ __forceinline__ void ldsm4(uint32_t (&r)[4], uint32_t addr) {
    asm volatile("ldmatrix.sync.aligned.m8n8.x4.shared.b16 {%0,%1,%2,%3}, [%4];"
                 : "=r"(r[0]), "=r"(r[1]), "=r"(r[2]), "=r"(r[3]) : "r"(addr));
}
__device__ __forceinline__ void mma_bf16(float (&d)[4], const uint32_t (&a)[4],
                                         uint32_t b0, uint32_t b1) {
    asm volatile("mma.sync.aligned.m16n8k16.row.col.f32.bf16.bf16.f32 "
                 "{%0,%1,%2,%3}, {%4,%5,%6,%7}, {%8,%9}, {%0,%1,%2,%3};"
                 : "+f"(d[0]), "+f"(d[1]), "+f"(d[2]), "+f"(d[3])
                 : "r"(a[0]), "r"(a[1]), "r"(a[2]), "r"(a[3]), "r"(b0), "r"(b1));
}

// ------------------------- top-k (exact, sorted like lax.top_k) ---------------
__device__ __forceinline__ unsigned int f2u(float f) {
    unsigned int u = __float_as_uint(f);
    return (u & 0x80000000u) ? ~u : (u | 0x80000000u);
}

__global__ void topk_kernel(const float* __restrict__ scores, int* __restrict__ out_idx) {
    const int b = blockIdx.x;
    const float* s = scores + (size_t)b * NPTS;
    __shared__ unsigned int hist[256];
    __shared__ unsigned int sh_prefix;
    __shared__ int sh_k;
    __shared__ int n_gt, n_eq;
    __shared__ unsigned long long keys[KSEL];
    __shared__ unsigned int eqi[KSEL];
    const int tid = threadIdx.x;   // 256

    if (tid == 0) { sh_prefix = 0u; sh_k = KSEL; }
    __syncthreads();
    for (int shift = 24; shift >= 0; shift -= 8) {
        hist[tid] = 0u;
        __syncthreads();
        unsigned int pref = sh_prefix;
        unsigned int mhi = (shift == 24) ? 0u : (0xFFFFFFFFu << (shift + 8));
        for (int i = tid; i < NPTS; i += 256) {
            unsigned int u = f2u(s[i]);
            if ((u & mhi) == pref) atomicAdd(&hist[(u >> shift) & 0xFFu], 1u);
        }
        __syncthreads();
        if (tid == 0) {
            int rem = sh_k;
            int byte = 255;
            for (; byte > 0; byte--) {
                int c = (int)hist[byte];
                if (rem <= c) break;
                rem -= c;
            }
            sh_k = rem;
            sh_prefix = pref | ((unsigned int)byte << shift);
        }
        __syncthreads();
    }
    const unsigned int uth = sh_prefix;

    if (tid == 0) { n_gt = 0; n_eq = 0; }
    __syncthreads();
    for (int i = tid; i < NPTS; i += 256) {
        unsigned int u = f2u(s[i]);
        if (u > uth) {
            int p = atomicAdd(&n_gt, 1);
            keys[p] = ((unsigned long long)u << 32) | (unsigned int)(~i);
        } else if (u == uth) {
            int p = atomicAdd(&n_eq, 1);
            if (p < KSEL) eqi[p] = (unsigned int)i;
        }
    }
    __syncthreads();
    const int cgt = n_gt;
    const int ceq = n_eq < KSEL ? n_eq : KSEL;
    for (int i = tid; i < KSEL; i += 256) if (i >= ceq) eqi[i] = 0xFFFFFFFFu;
    __syncthreads();
    for (int size = 2; size <= KSEL; size <<= 1)
        for (int stride = size >> 1; stride >= 1; stride >>= 1) {
            __syncthreads();
            int low = tid & (stride - 1);
            int i = ((tid - low) << 1) | low;
            int j = i | stride;
            unsigned int a = eqi[i], c = eqi[j];
            bool asc = ((i & size) == 0);
            if (asc ? (a > c) : (a < c)) { eqi[i] = c; eqi[j] = a; }
        }
    __syncthreads();
    const int need = KSEL - cgt;
    for (int t = tid; t < need; t += 256)
        keys[cgt + t] = ((unsigned long long)uth << 32) | (unsigned int)(~eqi[t]);
    __syncthreads();
    for (int size = 2; size <= KSEL; size <<= 1)
        for (int stride = size >> 1; stride >= 1; stride >>= 1) {
            __syncthreads();
            int low = tid & (stride - 1);
            int i = ((tid - low) << 1) | low;
            int j = i | stride;
            unsigned long long a = keys[i], c = keys[j];
            bool desc = ((i & size) == 0);
            if (desc ? (a < c) : (a > c)) { keys[i] = c; keys[j] = a; }
        }
    __syncthreads();
    for (int i = tid; i < KSEL; i += 256)
        out_idx[b * KSEL + i] = (int)(~(unsigned int)(keys[i] & 0xFFFFFFFFu));
}

// ------------------------- fp32 -> bf16 hi/lo converters ----------------------
__device__ __forceinline__ void split_bf16(float f, __nv_bfloat16& h, __nv_bfloat16& l) {
    h = __float2bfloat16_rn(f);
    l = __float2bfloat16_rn(f - __bfloat162float(h));
}

__global__ void convert_weights(const float* __restrict__ pw, const float* __restrict__ ipw) {
    const int NW1 = EDIM * DFEAT;          // proj_w
    const int NW2 = EDIM * EDIM;           // wk / wv
    for (int i = blockIdx.x * blockDim.x + threadIdx.x; i < NW1 + 2 * NW2;
         i += gridDim.x * blockDim.x) {
        __nv_bfloat16 h, l;
        if (i < NW1) {
            split_bf16(pw[i], h, l);
            g_wphi[i] = h; g_wplo[i] = l;
        } else if (i < NW1 + NW2) {
            int j = i - NW1;
            split_bf16(ipw[EDIM * EDIM + j], h, l);
            g_wkhi[j] = h; g_wklo[j] = l;
        } else {
            int j = i - NW1 - NW2;
            split_bf16(ipw[2 * EDIM * EDIM + j], h, l);
            g_wvhi[j] = h; g_wvlo[j] = l;
        }
    }
}

// gather top-k rows of per_point_features into bf16 hi/lo [8192 x 256]
__global__ void gather_convert(const float* __restrict__ ppf, const int* __restrict__ idx) {
    const int r = blockIdx.x * 4 + (threadIdx.x >> 6);   // 0..8191
    const int d = (threadIdx.x & 63) * 4;
    const int b = r >> 9;
    const float* src = ppf + ((size_t)b * NPTS + (size_t)idx[r]) * DFEAT;
    float4 f = *(const float4*)(src + d);
    __nv_bfloat16 h0,h1,h2,h3,l0,l1,l2,l3;
    split_bf16(f.x,h0,l0); split_bf16(f.y,h1,l1);
    split_bf16(f.z,h2,l2); split_bf16(f.w,h3,l3);
    size_t o = (size_t)r * DFEAT + d;
    *(__nv_bfloat162*)&g_ahi[o]     = __nv_bfloat162{h0,h1};
    *(__nv_bfloat162*)&g_ahi[o + 2] = __nv_bfloat162{h2,h3};
    *(__nv_bfloat162*)&g_alo[o]     = __nv_bfloat162{l0,l1};
    *(__nv_bfloat162*)&g_alo[o + 2] = __nv_bfloat162{l2,l3};
}

// ------------------------- split-bf16 tensor-core GEMM ------------------------
// C[M, 512] = (Ahi+Alo)[M,K] @ (Bhi+Blo)[512,K]^T + bias
// CTA tile 128x128, 8 warps as 4(m) x 2(n), warp tile 32x64.
// mma.sync m16n8k16 bf16, split products: hi*hi + hi*lo + lo*hi.
// EPI 0: fp32 C.  EPI 1: bf16 hi/lo C + fp32 rows (t<16) compacted into Cfp.
#define SA_HI 0
#define SA_LO 16384
#define SB_HI 32768
#define SB_LO 49152
#define MGEMM_SMEM 65536

template<int EPI>
__global__ void __launch_bounds__(256, 2)
mma_gemm(const __nv_bfloat16* __restrict__ Ahi, const __nv_bfloat16* __restrict__ Alo,
         const __nv_bfloat16* __restrict__ Bhi, const __nv_bfloat16* __restrict__ Blo,
         const float* __restrict__ bias, int K,
         float* __restrict__ Cfp, __nv_bfloat16* __restrict__ Chi, __nv_bfloat16* __restrict__ Clo)
{
    extern __shared__ char sm[];
    const uint32_t smb = smem_u32(sm);
    const int tid  = threadIdx.x;
    const int wid  = tid >> 5;
    const int lane = tid & 31;
    const int wm = wid & 3;          // 4 m-warps, 32 rows each
    const int wn = wid >> 2;         // 2 n-warps, 64 cols each
    const int mbase = blockIdx.x * 128;
    const int nbase = blockIdx.y * 128;

    float acc[2][8][4];
    #pragma unroll
    for (int i = 0; i < 2; i++)
        #pragma unroll
        for (int j = 0; j < 8; j++)
            #pragma unroll
            for (int t = 0; t < 4; t++) acc[i][j][t] = 0.f;

    // per-lane ldmatrix row/col components (row-relative, swizzle xor by row&7)
    const int arow_l = (lane & 7) + ((lane >> 3) & 1) * 8;   // A: within 16-row tile
    const int akb_l  = (lane >> 4) * 16;                      // A: 16B half select
    const int brow_l = (lane & 7) + ((lane >> 4) & 1) * 8;   // B: within 16-row pair
    const int bkb_l  = ((lane >> 3) & 1) * 16;

    const int ldrow = tid >> 3;           // 0..31 (per pass)
    const int ldq   = tid & 7;            // 16B chunk in row
    const uint32_t ldoff_base = (uint32_t)(ldq * 16);

    const int nch = K >> 6;
    for (int c = 0; c < nch; c++) {
        __syncthreads();
        #pragma unroll
        for (int p = 0; p < 4; p++) {
            int row = p * 32 + ldrow;
            uint32_t off = (uint32_t)(row * 128) + SWZ(ldoff_base ^ (uint32_t)((row & 7) << 4));
            // note: SWZ(row*128+q16) = row*128 + (q16 ^ ((row&7)<<4)); q16<128
            uint32_t o2 = (uint32_t)(row * 128) + ((ldoff_base) ^ (uint32_t)((row & 7) << 4));
            (void)off;
            size_t srca = (size_t)(mbase + row) * K + c * 64 + ldq * 8;
            size_t srcb = (size_t)(nbase + row) * K + c * 64 + ldq * 8;
            *(uint4*)(sm + SA_HI + o2) = *(const uint4*)(Ahi + srca);
            *(uint4*)(sm + SA_LO + o2) = *(const uint4*)(Alo + srca);
            *(uint4*)(sm + SB_HI + o2) = *(const uint4*)(Bhi + srcb);
            *(uint4*)(sm + SB_LO + o2) = *(const uint4*)(Blo + srcb);
        }
        __syncthreads();

        #pragma unroll
        for (int kk = 0; kk < 4; kk++) {
            uint32_t ah[2][4], al[2][4];
            #pragma unroll
            for (int mt = 0; mt < 2; mt++) {
                int row = wm * 32 + mt * 16 + arow_l;
                uint32_t kb = (uint32_t)(kk * 32 + akb_l) ^ (uint32_t)((row & 7) << 4);
                uint32_t ad = (uint32_t)(row * 128) + kb;
                ldsm4(ah[mt], smb + SA_HI + ad);
                ldsm4(al[mt], smb + SA_LO + ad);
            }
            #pragma unroll
            for (int np = 0; np < 4; np++) {
                int row = wn * 64 + np * 16 + brow_l;
                uint32_t kb = (uint32_t)(kk * 32 + bkb_l) ^ (uint32_t)((row & 7) << 4);
                uint32_t bd = (uint32_t)(row * 128) + kb;
                uint32_t bh[4], bl[4];
                ldsm4(bh, smb + SB_HI + bd);
                ldsm4(bl, smb + SB_LO + bd);
                #pragma unroll
                for (int mt = 0; mt < 2; mt++) {
                    mma_bf16(acc[mt][2*np],   ah[mt], bh[0], bh[1]);
                    mma_bf16(acc[mt][2*np+1], ah[mt], bh[2], bh[3]);
                    mma_bf16(acc[mt][2*np],   ah[mt], bl[0], bl[1]);
                    mma_bf16(acc[mt][2*np+1], ah[mt], bl[2], bl[3]);
                    mma_bf16(acc[mt][2*np],   al[mt], bh[0], bh[1]);
                    mma_bf16(acc[mt][2*np+1], al[mt], bh[2], bh[3]);
                }
            }
        }
    }

    // ---------------- epilogue ----------------
    const int rrow = lane >> 2;
    const int rcol = (lane & 3) * 2;
    #pragma unroll
    for (int mt = 0; mt < 2; mt++) {
        #pragma unroll
        for (int nt = 0; nt < 8; nt++) {
            int col = nbase + wn * 64 + nt * 8 + rcol;
            float b0 = bias[col], b1 = bias[col + 1];
            #pragma unroll
            for (int h = 0; h < 2; h++) {   // h=0 -> c0,c1 ; h=1 -> c2,c3
                int r = mbase + wm * 32 + mt * 16 + rrow + h * 8;
                float v0 = acc[mt][nt][2*h]   + b0;
                float v1 = acc[mt][nt][2*h+1] + b1;
                if (EPI == 0) {
                    *(float2*)&Cfp[(size_t)r * EDIM + col] = make_float2(v0, v1);
                } else {
                    __nv_bfloat16 h0, h1, l0, l1;
                    split_bf16(v0, h0, l0); split_bf16(v1, h1, l1);
                    size_t o = (size_t)r * EDIM + col;
                    *(__nv_bfloat162*)&Chi[o] = __nv_bfloat162{h0, h1};
                    *(__nv_bfloat162*)&Clo[o] = __nv_bfloat162{l0, l1};
                    int t = r & 511, bb = r >> 9;
                    if (t < TOUT) {
                        size_t oq = (size_t)(bb * TOUT + t) * EDIM + col;
                        *(float2*)&Cfp[oq] = make_float2(v0, v1);
                    }
                }
            }
        }
    }
}

// ------------------------- fp32 tiled SGEMM (small GEMMs) --------------------
__global__ void __launch_bounds__(256)
sgemm_kernel(const float* __restrict__ A, const float* __restrict__ Bw,
             const float* __restrict__ bias, float* __restrict__ C,
             int M, int Nc, int Kd)
{
    __shared__ float s_a[16][64];
    __shared__ float s_b[16][64];
    const int tid = threadIdx.x;
    const int tx = tid & 15, ty = tid >> 4;
    const int bm = blockIdx.x * 64, bn = blockIdx.y * 64;
    const int lm = tid & 63;
    const int lk = (tid >> 6) << 2;

    const float* arow = A + (size_t)(bm + lm) * Kd;
    const float* brow = Bw + (size_t)(bn + lm) * Kd;

    float acc[4][4] = {};
    for (int k0 = 0; k0 < Kd; k0 += 16) {
        float4 a4 = *(const float4*)(arow + k0 + lk);
        float4 b4 = *(const float4*)(brow + k0 + lk);
        __syncthreads();
        s_a[lk + 0][lm] = a4.x; s_a[lk + 1][lm] = a4.y;
        s_a[lk + 2][lm] = a4.z; s_a[lk + 3][lm] = a4.w;
        s_b[lk + 0][lm] = b4.x; s_b[lk + 1][lm] = b4.y;
        s_b[lk + 2][lm] = b4.z; s_b[lk + 3][lm] = b4.w;
        __syncthreads();
        #pragma unroll
        for (int kk = 0; kk < 16; kk++) {
            float4 av = *(const float4*)&s_a[kk][ty << 2];
            float4 bv = *(const float4*)&s_b[kk][tx << 2];
            float ar[4] = {av.x, av.y, av.z, av.w};
            float br[4] = {bv.x, bv.y, bv.z, bv.w};
            #pragma unroll
            for (int i = 0; i < 4; i++)
                #pragma unroll
                for (int j = 0; j < 4; j++)
                    acc[i][j] += ar[i] * br[j];
        }
    }
    #pragma unroll
    for (int i = 0; i < 4; i++) {
        int row = bm + (ty << 2) + i;
        #pragma unroll
        for (int j = 0; j < 4; j++) {
            int col = bn + (tx << 2) + j;
            C[(size_t)row * Nc + col] = acc[i][j] + bias[col];
        }
    }
}

// ------------------------- attention (16 queries x 512 keys per (b,h)) -------
#define ATTN_SMEM ((16*64 + 16*512 + 128*65) * 4)

__global__ void attn_kernel(const float* __restrict__ qb, const float* __restrict__ kb,
                            const float* __restrict__ vb, float* __restrict__ ob)
{
    extern __shared__ float smf[];
    float* s_q  = smf;
    float* s_l  = smf + 16 * 64;
    float* s_kv = smf + 16 * 64 + 16 * 512;
    const int b = blockIdx.x >> 3, h = blockIdx.x & 7;
    const int tid = threadIdx.x;            // 128

    const float* qbase = qb + ((size_t)b * TOUT) * EDIM + h * DH;
    for (int i = tid; i < 16 * 64; i += 128) {
        int t = i >> 6, d = i & 63;
        s_q[i] = qbase[(size_t)t * EDIM + d];
    }
    const float scale = 0.125f;

    for (int c = 0; c < 4; c++) {
        const float* kbase = kb + ((size_t)(b * KSEL + c * 128)) * EDIM + h * DH;
        __syncthreads();
        for (int i = tid; i < 128 * 64; i += 128) {
            int j = i >> 6, d = i & 63;
            s_kv[j * 65 + d] = kbase[(size_t)j * EDIM + d];
        }
        __syncthreads();
        {
            int j = tid;
            float acc[16];
            #pragma unroll
            for (int t = 0; t < 16; t++) acc[t] = 0.f;
            for (int d = 0; d < 64; d++) {
                float kd = s_kv[j * 65 + d];
                #pragma unroll
                for (int t = 0; t < 16; t++) acc[t] += s_q[t * 64 + d] * kd;
            }
            #pragma unroll
            for (int t = 0; t < 16; t++) s_l[t * 512 + c * 128 + j] = acc[t] * scale;
        }
    }
    __syncthreads();

    {
        int row = tid >> 3, l = tid & 7;
        float* lr = s_l + row * 512;
        float m = -1e30f;
        for (int j = l; j < 512; j += 8) m = fmaxf(m, lr[j]);
        for (int o = 4; o >= 1; o >>= 1) m = fmaxf(m, __shfl_xor_sync(0xffffffffu, m, o));
        float sum = 0.f;
        for (int j = l; j < 512; j += 8) { float e = expf(lr[j] - m); lr[j] = e; sum += e; }
        for (int o = 4; o >= 1; o >>= 1) sum += __shfl_xor_sync(0xffffffffu, sum, o);
        float inv = 1.f / sum;
        for (int j = l; j < 512; j += 8) lr[j] *= inv;
    }

    {
        int d = tid & 63, tb = (tid >> 6) << 3;
        float acc[8];
        #pragma unroll
        for (int t = 0; t < 8; t++) acc[t] = 0.f;
        for (int c = 0; c < 4; c++) {
            const float* vbase = vb + ((size_t)(b * KSEL + c * 128)) * EDIM + h * DH;
            __syncthreads();
            for (int i = tid; i < 128 * 64; i += 128) {
                int j = i >> 6, dd = i & 63;
                s_kv[j * 65 + dd] = vbase[(size_t)j * EDIM + dd];
            }
            __syncthreads();
            for (int j = 0; j < 128; j++) {
                float vv = s_kv[j * 65 + d];
                #pragma unroll
                for (int t = 0; t < 8; t++) acc[t] += s_l[(tb + t) * 512 + c * 128 + j] * vv;
            }
        }
        float* obase = ob + ((size_t)b * TOUT) * EDIM + h * DH;
        #pragma unroll
        for (int t = 0; t < 8; t++) obase[(size_t)(tb + t) * EDIM + d] = acc[t];
    }
}

// ------------------------- residual + layernorm ------------------------------
__global__ void ln_kernel(const float* __restrict__ xq, const float* __restrict__ o2,
                          const float* __restrict__ g, const float* __restrict__ be,
                          float* __restrict__ y)
{
    const int r = blockIdx.x;            // 0..255
    const float* xr = xq + (size_t)r * EDIM;
    const float* orow = o2 + (size_t)r * EDIM;
    const int tid = threadIdx.x;         // 256
    float v0 = xr[tid] + orow[tid];
    float v1 = xr[tid + 256] + orow[tid + 256];
    float s = v0 + v1, sq = v0 * v0 + v1 * v1;
    for (int o = 16; o >= 1; o >>= 1) {
        s  += __shfl_xor_sync(0xffffffffu, s, o);
        sq += __shfl_xor_sync(0xffffffffu, sq, o);
    }
    __shared__ float ss[8], ssq[8];
    __shared__ float mu, rstd;
    int w = tid >> 5;
    if ((tid & 31) == 0) { ss[w] = s; ssq[w] = sq; }
    __syncthreads();
    if (tid == 0) {
        float S = 0.f, SQ = 0.f;
        for (int i = 0; i < 8; i++) { S += ss[i]; SQ += ssq[i]; }
        float m = S / 512.f;
        float var = SQ / 512.f - m * m;
        mu = m; rstd = rsqrtf(var + 1e-5f);
    }
    __syncthreads();
    y[(size_t)r * EDIM + tid]       = (v0 - mu) * rstd * g[tid]       + be[tid];
    y[(size_t)r * EDIM + tid + 256] = (v1 - mu) * rstd * g[tid + 256] + be[tid + 256];
}

// ------------------------- FFN residual + exact GELU -------------------------
__global__ void final_kernel(const float* __restrict__ y, const float* __restrict__ z,
                             float* __restrict__ out)
{
    int i = blockIdx.x * blockDim.x + threadIdx.x;
    float zz = z[i];
    float ge = 0.5f * zz * (1.f + erff(zz * 0.70710678118654752f));
    out[i] = y[i] + ge;
}

// ------------------------- launcher ------------------------------------------
extern "C" void kernel_launch(void* const* d_in, const int* in_sizes, int n_in,
                              void* d_out, int out_size)
{
    const float* ppf = (const float*)d_in[0];
    const float* sc  = (const float*)d_in[1];
    const float* pw  = (const float*)d_in[2];
    const float* pb  = (const float*)d_in[3];
    const float* ipw = (const float*)d_in[4];
    const float* ipb = (const float*)d_in[5];
    const float* opw = (const float*)d_in[6];
    const float* opb = (const float*)d_in[7];
    const float* lng = (const float*)d_in[8];
    const float* lnb = (const float*)d_in[9];
    const float* fw  = (const float*)d_in[10];
    const float* fb  = (const float*)d_in[11];
    float* out = (float*)d_out;

    int* idx;
    __nv_bfloat16 *ahi, *alo, *wphi, *wplo, *wkhi, *wklo, *wvhi, *wvlo, *xhi, *xlo;
    float *k, *v, *xq, *q, *o, *o2, *y, *z;
    cudaGetSymbolAddress((void**)&idx,  g_idx);
    cudaGetSymbolAddress((void**)&ahi,  g_ahi);
    cudaGetSymbolAddress((void**)&alo,  g_alo);
    cudaGetSymbolAddress((void**)&wphi, g_wphi);
    cudaGetSymbolAddress((void**)&wplo, g_wplo);
    cudaGetSymbolAddress((void**)&wkhi, g_wkhi);
    cudaGetSymbolAddress((void**)&wklo, g_wklo);
    cudaGetSymbolAddress((void**)&wvhi, g_wvhi);
    cudaGetSymbolAddress((void**)&wvlo, g_wvlo);
    cudaGetSymbolAddress((void**)&xhi,  g_xhi);
    cudaGetSymbolAddress((void**)&xlo,  g_xlo);
    cudaGetSymbolAddress((void**)&k,    g_k);
    cudaGetSymbolAddress((void**)&v,    g_v);
    cudaGetSymbolAddress((void**)&xq,   g_xq);
    cudaGetSymbolAddress((void**)&q,    g_q);
    cudaGetSymbolAddress((void**)&o,    g_o);
    cudaGetSymbolAddress((void**)&o2,   g_o2);
    cudaGetSymbolAddress((void**)&y,    g_y);
    cudaGetSymbolAddress((void**)&z,    g_z);

    cudaFuncSetAttribute(mma_gemm<0>, cudaFuncAttributeMaxDynamicSharedMemorySize, MGEMM_SMEM);
    cudaFuncSetAttribute(mma_gemm<1>, cudaFuncAttributeMaxDynamicSharedMemorySize, MGEMM_SMEM);
    cudaFuncSetAttribute(attn_kernel, cudaFuncAttributeMaxDynamicSharedMemorySize, ATTN_SMEM);

    // 1) exact sorted top-512 indices per batch
    topk_kernel<<<16, 256>>>(sc, idx);

    // 1b) weight + gathered-feature bf16 hi/lo conversion
    convert_weights<<<512, 256>>>(pw, ipw);
    gather_convert<<<2048, 256>>>(ppf, idx);

    // 2) x = gather @ proj_w^T + pb  -> x as bf16 hi/lo (+ fp32 xq rows t<16)
    mma_gemm<1><<<dim3(64, 4), 256, MGEMM_SMEM>>>(ahi, alo, wphi, wplo, pb, DFEAT, xq, xhi, xlo);

    // 3) k, v = x @ W^T + b  (tensor cores, fp32 output)
    mma_gemm<0><<<dim3(64, 4), 256, MGEMM_SMEM>>>(xhi, xlo, wkhi, wklo, ipb + EDIM,     EDIM, k, nullptr, nullptr);
    mma_gemm<0><<<dim3(64, 4), 256, MGEMM_SMEM>>>(xhi, xlo, wvhi, wvlo, ipb + 2 * EDIM, EDIM, v, nullptr, nullptr);

    // 4) q only for the first 16 tokens per batch  [256, 512]
    sgemm_kernel<<<dim3(4, 8), 256>>>(xq, ipw, ipb, q, 256, 512, 512);

    // 5) attention
    attn_kernel<<<128, 128, ATTN_SMEM>>>(q, k, v, o);

    // 6) out_proj on 256 rows
    sgemm_kernel<<<dim3(4, 8), 256>>>(o, opw, opb, o2, 256, 512, 512);

    // 7) residual + layernorm
    ln_kernel<<<256, 256>>>(xq, o2, lng, lnb, y);

    // 8) FFN + residual + exact GELU
    sgemm_kernel<<<dim3(4, 8), 256>>>(y, fw, fb, z, 256, 512, 512);
    final_kernel<<<512, 256>>>(y, z, out);
}